// round 13
// baseline (speedup 1.0000x reference)
#include <cuda_runtime.h>
#include <cuda_bf16.h>
#include <cstdint>
#include <math.h>

#define E_   30
#define NB_  12
#define F_   1024
#define H_   32
#define B_   8192
#define L_   128
#define EPS_ 1e-12f

#define EPC   2
#define NEG   15
#define ROWS  256
#define FROWS 160          // fma rows (warps 0-4)
#define TROWS 96           // tensor rows (warps 5-7)
#define KC    32
#define NCH   (F_ / KC)

__device__ float g_w[E_ * B_ * NB_];
__device__ float g_XT[F_ * B_];                    // X transposed (F,B)
__device__ __nv_bfloat16 g_Xh[B_ * F_], g_Xl[B_ * F_];

// ---- per-buffer smem offsets (bytes) ----
#define OXF32 0          // 32 k x 160 cols f32 = 20480
#define OXHI  20480      // 96 rows x 80B
#define OXLO  28160
#define OWF32 35840      // 2e x 32 x 128B = 8192
#define OWHI  44032      // 2e x 32 x 80B = 5120
#define OWLO  49152
#define BUFSZ 54272
#define SMEM_BYTES (2 * BUFSZ)      // 108544
// epilogue aliases
#define EP_HS  0                    // 2e x 256 x 33 f32 = 67584
#define EP_W2  69632
#define EP_B2  72704
#define EP_BW  72832

__device__ __forceinline__ uint32_t smem_u32(const void* p) {
    uint32_t a;
    asm("{ .reg .u64 t; cvta.to.shared.u64 t, %1; cvt.u32.u64 %0, t; }"
        : "=r"(a) : "l"(p));
    return a;
}
#define CP16(dst, src) \
    asm volatile("cp.async.cg.shared.global [%0], [%1], 16;" \
        :: "r"((uint32_t)(dst)), "l"(src) : "memory")
#define CPCOMMIT() asm volatile("cp.async.commit_group;" ::: "memory")
#define CPWAIT0()  asm volatile("cp.async.wait_group 0;" ::: "memory")
#define BARSYNC()  asm volatile("barrier.sync 0;" ::: "memory")

__device__ __forceinline__ void ldmx4(uint32_t* r, uint32_t a) {
    asm volatile("ldmatrix.sync.aligned.m8n8.x4.shared.b16 {%0,%1,%2,%3}, [%4];"
        : "=r"(r[0]), "=r"(r[1]), "=r"(r[2]), "=r"(r[3]) : "r"(a));
}
__device__ __forceinline__ void ldmx4t(uint32_t* r, uint32_t a) {
    asm volatile("ldmatrix.sync.aligned.m8n8.x4.trans.shared.b16 {%0,%1,%2,%3}, [%4];"
        : "=r"(r[0]), "=r"(r[1]), "=r"(r[2]), "=r"(r[3]) : "r"(a));
}
__device__ __forceinline__ void mma_bf16(float* c, const uint32_t* a, const uint32_t* b) {
    asm volatile(
        "mma.sync.aligned.m16n8k16.row.col.f32.bf16.bf16.f32 "
        "{%0,%1,%2,%3}, {%4,%5,%6,%7}, {%8,%9}, {%0,%1,%2,%3};"
        : "+f"(c[0]), "+f"(c[1]), "+f"(c[2]), "+f"(c[3])
        : "r"(a[0]), "r"(a[1]), "r"(a[2]), "r"(a[3]), "r"(b[0]), "r"(b[1]));
}
__device__ __forceinline__ void fma2(unsigned long long& d,
                                     unsigned long long a, unsigned long long b) {
    asm("fma.rn.f32x2 %0, %1, %2, %0;" : "+l"(d) : "l"(a), "l"(b));
}
__device__ __forceinline__ unsigned long long pack2(float lo, float hi) {
    unsigned long long r;
    asm("mov.b64 %0, {%1, %2};" : "=l"(r) : "f"(lo), "f"(hi));
    return r;
}
__device__ __forceinline__ void unpack2(float& lo, float& hi, unsigned long long v) {
    asm("mov.b64 {%0, %1}, %2;" : "=f"(lo), "=f"(hi) : "l"(v));
}
__device__ __forceinline__ void split2(float x, float y, uint32_t& hi, uint32_t& lo) {
    __nv_bfloat16 hx = __float2bfloat16(x);
    __nv_bfloat16 hy = __float2bfloat16(y);
    __nv_bfloat16 lx = __float2bfloat16(x - __bfloat162float(hx));
    __nv_bfloat16 ly = __float2bfloat16(y - __bfloat162float(hy));
    hi = (uint32_t)__bfloat16_as_ushort(hx) | ((uint32_t)__bfloat16_as_ushort(hy) << 16);
    lo = (uint32_t)__bfloat16_as_ushort(lx) | ((uint32_t)__bfloat16_as_ushort(ly) << 16);
}
__device__ __forceinline__ float selu(float v) {
    const float S  = 1.0507009873554805f;
    const float SA = 1.0507009873554805f * 1.6732632423543772f;
    return (v > 0.f) ? S * v : SA * (__expf(v) - 1.f);
}

// ---------------------------------------------------------------------------
// Prep: XT = X^T, plus bf16 hi/lo split of X. grid (F/32, B/32), 256 thr.
// ---------------------------------------------------------------------------
__global__ __launch_bounds__(256) void prep_kernel(const float* __restrict__ X) {
    __shared__ float t[32][33];
    const int fx = blockIdx.x * 32, by = blockIdx.y * 32;
    const int lx = threadIdx.x & 31, ly = threadIdx.x >> 5;
    #pragma unroll
    for (int i = 0; i < 32; i += 8) {
        size_t gi = (size_t)(by + ly + i) * F_ + fx + lx;
        float v = X[gi];
        t[ly + i][lx] = v;
        __nv_bfloat16 h = __float2bfloat16(v);
        g_Xh[gi] = h;
        g_Xl[gi] = __float2bfloat16(v - __bfloat162float(h));
    }
    __syncthreads();
    #pragma unroll
    for (int i = 0; i < 32; i += 8)
        g_XT[(size_t)(fx + ly + i) * B_ + by + lx] = t[lx][ly + i];
}

// ---------------------------------------------------------------------------
// Kernel A: hybrid dual-pipe MLP. grid (32, 15), 256 thr, 2 CTAs/SM.
// ---------------------------------------------------------------------------
__global__ void __launch_bounds__(256, 2) mlp_hybrid_kernel(
    const float* __restrict__ X,
    const float* __restrict__ bw,
    const float* __restrict__ W1,
    const float* __restrict__ b1,
    const float* __restrict__ W2,
    const float* __restrict__ b2)
{
    extern __shared__ char smem[];
    const uint32_t sb = smem_u32(smem);
    const int tid  = threadIdx.x;
    const int w    = tid >> 5;
    const int lane = tid & 31;
    const int b0   = blockIdx.x * ROWS;
    const int e0   = blockIdx.y * EPC;

    // staging lambdas
    const int xkq = tid / 40, xcq = tid % 40;          // fma X mapping
    auto fma_stage = [&](int c, int p) {               // tid < 160, all cp.async
        const int k0 = c * KC;
        const uint32_t bb = sb + p * BUFSZ;
        #pragma unroll
        for (int it = 0; it < 8; it++) {
            int kk = it * 4 + xkq;
            CP16(bb + OXF32 + kk * 640 + xcq * 16,
                 g_XT + (size_t)(k0 + kk) * B_ + b0 + xcq * 4);
        }
        #pragma unroll
        for (int it = 0; it < 4; it++) {
            int g = it * 160 + tid;
            if (g < 512) {
                int e = g >> 8, r = g & 255, kr = r >> 3, q = r & 7;
                CP16(bb + OWF32 + e * 4096 + kr * 128 + q * 16,
                     W1 + ((size_t)(e0 + e) * F_ + k0 + kr) * H_ + q * 4);
            }
        }
    };
    const int tid_t = tid - FROWS;                     // tensor local tid (0..95)
    auto tensor_stageX = [&](int c, int p) {
        const int k0 = c * KC;
        const uint32_t bb = sb + p * BUFSZ;
        #pragma unroll
        for (int it = 0; it < 8; it++) {
            int t = it * 96 + tid_t;
            if (t < 384) {
                int row = t >> 2, q = t & 3;
                CP16(bb + OXHI + row * 80 + q * 16,
                     g_Xh + (size_t)(b0 + FROWS + row) * F_ + k0 + q * 8);
            } else {
                int t2 = t - 384;
                int row = t2 >> 2, q = t2 & 3;
                CP16(bb + OXLO + row * 80 + q * 16,
                     g_Xl + (size_t)(b0 + FROWS + row) * F_ + k0 + q * 8);
            }
        }
    };
    auto tensor_ldgW = [&](float4* wv, int c) {
        const int k0 = c * KC;
        #pragma unroll
        for (int it = 0; it < 6; it++) {
            int g = it * 96 + tid_t;
            if (g < 512) {
                int e = g >> 8, r = g & 255, kr = r >> 3, q = r & 7;
                wv[it] = *reinterpret_cast<const float4*>(
                    &W1[((size_t)(e0 + e) * F_ + k0 + kr) * H_ + q * 4]);
            }
        }
    };
    auto tensor_stsW = [&](const float4* wv, int p) {
        const uint32_t bb = sb + p * BUFSZ;
        #pragma unroll
        for (int it = 0; it < 6; it++) {
            int g = it * 96 + tid_t;
            if (g < 512) {
                int e = g >> 8, r = g & 255, kr = r >> 3, q = r & 7;
                uint32_t h01, l01, h23, l23;
                split2(wv[it].x, wv[it].y, h01, l01);
                split2(wv[it].z, wv[it].w, h23, l23);
                int off = e * 2560 + kr * 80 + q * 8;
                *reinterpret_cast<uint2*>(smem + (bb - sb) + OWHI + off) = make_uint2(h01, h23);
                *reinterpret_cast<uint2*>(smem + (bb - sb) + OWLO + off) = make_uint2(l01, l23);
            }
        }
    };

    float* Hsf = (float*)(smem + EP_HS);

    if (w < 5) {
        // ================= FMA ROLE: rows 0..159, fp32 FFMA2 =================
        const int rowt = tid >> 2, colg = tid & 3;
        fma_stage(0, 0); CPCOMMIT(); CPWAIT0(); BARSYNC();

        unsigned long long accf[EPC][4][4];
        #pragma unroll
        for (int e = 0; e < EPC; e++)
            #pragma unroll
            for (int j = 0; j < 4; j++)
                #pragma unroll
                for (int q = 0; q < 4; q++) accf[e][j][q] = 0ull;

        for (int c = 0; c < NCH; c++) {
            const int p = c & 1;
            if (c + 1 < NCH) { fma_stage(c + 1, p ^ 1); CPCOMMIT(); }
            const char* xb  = smem + p * BUFSZ + OXF32;
            const char* wbp = smem + p * BUFSZ + OWF32;
            #pragma unroll 4
            for (int kk = 0; kk < KC; kk++) {
                float4 a = *reinterpret_cast<const float4*>(xb + kk * 640 + rowt * 16);
                unsigned long long pa[4] = {
                    pack2(a.x, a.x), pack2(a.y, a.y),
                    pack2(a.z, a.z), pack2(a.w, a.w) };
                #pragma unroll
                for (int e = 0; e < EPC; e++) {
                    ulonglong2 wA = *reinterpret_cast<const ulonglong2*>(
                        wbp + e * 4096 + kk * 128 + colg * 32);
                    ulonglong2 wB = *reinterpret_cast<const ulonglong2*>(
                        wbp + e * 4096 + kk * 128 + colg * 32 + 16);
                    #pragma unroll
                    for (int j = 0; j < 4; j++) {
                        fma2(accf[e][j][0], pa[j], wA.x);
                        fma2(accf[e][j][1], pa[j], wA.y);
                        fma2(accf[e][j][2], pa[j], wB.x);
                        fma2(accf[e][j][3], pa[j], wB.y);
                    }
                }
            }
            CPWAIT0(); BARSYNC();
        }
        // store selu(acc+b1) -> Hs
        #pragma unroll
        for (int e = 0; e < EPC; e++)
            #pragma unroll
            for (int j = 0; j < 4; j++) {
                int r = rowt * 4 + j;
                #pragma unroll
                for (int q = 0; q < 4; q++) {
                    float v0, v1;
                    unpack2(v0, v1, accf[e][j][q]);
                    int c0 = colg * 8 + q * 2;
                    v0 += __ldg(&b1[(e0 + e) * H_ + c0]);
                    v1 += __ldg(&b1[(e0 + e) * H_ + c0 + 1]);
                    Hsf[e * 8448 + r * 33 + c0]     = selu(v0);
                    Hsf[e * 8448 + r * 33 + c0 + 1] = selu(v1);
                }
            }
    } else {
        // ================= TENSOR ROLE: rows 160..255, bf16x3 =================
        const int tw = w - 5;
        const int lr16 = lane & 15, lq16 = (lane >> 4) * 16;
        {
            float4 w0[6];
            tensor_ldgW(w0, 0);
            tensor_stageX(0, 0); CPCOMMIT();
            tensor_stsW(w0, 0);
            CPWAIT0(); BARSYNC();
        }
        float acct[EPC][2][4][4];
        #pragma unroll
        for (int e = 0; e < EPC; e++)
            #pragma unroll
            for (int mt = 0; mt < 2; mt++)
                #pragma unroll
                for (int nt = 0; nt < 4; nt++)
                    #pragma unroll
                    for (int j = 0; j < 4; j++) acct[e][mt][nt][j] = 0.f;

        float4 wv[6];
        for (int c = 0; c < NCH; c++) {
            const int p = c & 1;
            if (c + 1 < NCH) {
                tensor_ldgW(wv, c + 1);
                tensor_stageX(c + 1, p ^ 1); CPCOMMIT();
            }
            const uint32_t bb = sb + p * BUFSZ;
            #pragma unroll
            for (int ks = 0; ks < 2; ks++) {
                uint32_t Ah[2][4], Al[2][4];
                #pragma unroll
                for (int mt = 0; mt < 2; mt++) {
                    uint32_t ar = bb + OXHI +
                        (uint32_t)((tw * 32 + mt * 16 + lr16) * 80 + ks * 32 + lq16);
                    ldmx4(Ah[mt], ar);
                    ldmx4(Al[mt], ar + (OXLO - OXHI));
                }
                #pragma unroll
                for (int e = 0; e < EPC; e++) {
                    #pragma unroll
                    for (int np = 0; np < 2; np++) {
                        uint32_t br = bb + OWHI +
                            (uint32_t)(e * 2560 + (ks * 16 + lr16) * 80 + np * 32 + lq16);
                        uint32_t Bh[4], Bl[4];
                        ldmx4t(Bh, br);
                        ldmx4t(Bl, br + (OWLO - OWHI));
                        #pragma unroll
                        for (int mt = 0; mt < 2; mt++) {
                            #pragma unroll
                            for (int t = 0; t < 2; t++) {
                                float* C = acct[e][mt][np * 2 + t];
                                mma_bf16(C, Ah[mt], &Bh[t * 2]);
                                mma_bf16(C, Al[mt], &Bh[t * 2]);
                                mma_bf16(C, Ah[mt], &Bl[t * 2]);
                            }
                        }
                    }
                }
            }
            if (c + 1 < NCH) tensor_stsW(wv, p ^ 1);
            CPWAIT0(); BARSYNC();
        }
        // store selu(acc+b1) -> Hs
        #pragma unroll
        for (int e = 0; e < EPC; e++)
            #pragma unroll
            for (int mt = 0; mt < 2; mt++) {
                int r0 = FROWS + tw * 32 + mt * 16 + (lane >> 2);
                #pragma unroll
                for (int nt = 0; nt < 4; nt++) {
                    int col = nt * 8 + (lane & 3) * 2;
                    float ba = __ldg(&b1[(e0 + e) * H_ + col]);
                    float bb2 = __ldg(&b1[(e0 + e) * H_ + col + 1]);
                    const float* C = acct[e][mt][nt];
                    Hsf[e * 8448 + r0 * 33 + col]           = selu(C[0] + ba);
                    Hsf[e * 8448 + r0 * 33 + col + 1]       = selu(C[1] + bb2);
                    Hsf[e * 8448 + (r0 + 8) * 33 + col]     = selu(C[2] + ba);
                    Hsf[e * 8448 + (r0 + 8) * 33 + col + 1] = selu(C[3] + bb2);
                }
            }
    }
    BARSYNC();

    // stage layer-2 constants (region above Hs)
    float* W2s = (float*)(smem + EP_W2);
    float* b2s = (float*)(smem + EP_B2);
    float* bws = (float*)(smem + EP_BW);
    for (int t = tid; t < EPC * H_ * NB_; t += 256)
        W2s[t] = W2[(size_t)e0 * H_ * NB_ + t];
    if (tid < EPC * NB_) {
        b2s[tid] = b2[e0 * NB_ + tid];
        bws[tid] = bw[e0 * NB_ + tid];
    }
    BARSYNC();

    // layer 2 + weight update + signed-L1 normalize (row = tid)
    #pragma unroll
    for (int e = 0; e < EPC; e++) {
        float h[H_];
        #pragma unroll
        for (int hh = 0; hh < H_; hh++) h[hh] = Hsf[e * 8448 + tid * 33 + hh];

        float ew[NB_]; float s = 0.f;
        #pragma unroll
        for (int n = 0; n < NB_; n++) { ew[n] = __expf(bws[e * NB_ + n]); s += ew[n]; }
        const float inv_s = 1.f / fmaxf(s, EPS_);

        float upd[NB_]; float sa = 0.f;
        #pragma unroll
        for (int n = 0; n < NB_; n++) {
            float a2 = b2s[e * NB_ + n];
            #pragma unroll
            for (int hh = 0; hh < H_; hh++)
                a2 = fmaf(h[hh], W2s[e * H_ * NB_ + hh * NB_ + n], a2);
            float u = fmaf(ew[n], inv_s, a2);
            upd[n] = u;
            sa += fabsf(u);
        }
        const float inv = 1.f / fmaxf(sa, EPS_);

        float4* dst = reinterpret_cast<float4*>(
            &g_w[((size_t)(e0 + e) * B_ + b0 + tid) * NB_]);
        dst[0] = make_float4(upd[0] * inv, upd[1] * inv, upd[2]  * inv, upd[3]  * inv);
        dst[1] = make_float4(upd[4] * inv, upd[5] * inv, upd[6]  * inv, upd[7]  * inv);
        dst[2] = make_float4(upd[8] * inv, upd[9] * inv, upd[10] * inv, upd[11] * inv);
    }
}

// ---------------------------------------------------------------------------
// Kernel B: mixed = w @ D, softmax over L (|mixed| < 1 -> no max pass).
// ---------------------------------------------------------------------------
__global__ __launch_bounds__(128, 7) void mix_softmax_kernel(
    const float* __restrict__ D, float* __restrict__ out)
{
    const int warp = threadIdx.x >> 5;
    const int lane = threadIdx.x & 31;
    const size_t b = (size_t)blockIdx.x * 4 + warp;

    float4 Dreg[NB_];
    #pragma unroll
    for (int n = 0; n < NB_; n++)
        Dreg[n] = *reinterpret_cast<const float4*>(
            &D[(b * NB_ + n) * L_ + lane * 4]);

    const float* wp = &g_w[b * NB_];
    float wv_next = (lane < NB_) ? wp[lane] : 0.f;

    for (int e = 0; e < E_; e++) {
        float wv = wv_next;
        if (e + 1 < E_)
            wv_next = (lane < NB_) ? wp[(size_t)(e + 1) * B_ * NB_ + lane] : 0.f;

        float4 v = make_float4(0.f, 0.f, 0.f, 0.f);
        #pragma unroll
        for (int n = 0; n < NB_; n++) {
            float wn = __shfl_sync(0xffffffffu, wv, n);
            v.x = fmaf(wn, Dreg[n].x, v.x);
            v.y = fmaf(wn, Dreg[n].y, v.y);
            v.z = fmaf(wn, Dreg[n].z, v.z);
            v.w = fmaf(wn, Dreg[n].w, v.w);
        }
        float e0 = __expf(v.x), e1 = __expf(v.y);
        float e2 = __expf(v.z), e3 = __expf(v.w);
        float sm = (e0 + e1) + (e2 + e3);
        #pragma unroll
        for (int off = 16; off > 0; off >>= 1)
            sm += __shfl_xor_sync(0xffffffffu, sm, off);
        const float inv = 1.f / sm;
        *reinterpret_cast<float4*>(&out[((size_t)e * B_ + b) * L_ + lane * 4]) =
            make_float4(e0 * inv, e1 * inv, e2 * inv, e3 * inv);
    }
}

// ---------------------------------------------------------------------------
extern "C" void kernel_launch(void* const* d_in, const int* in_sizes, int n_in,
                              void* d_out, int out_size)
{
    const float* D  = (const float*)d_in[0];
    const float* X  = (const float*)d_in[1];
    const float* bw = (const float*)d_in[2];
    const float* W1 = (const float*)d_in[3];
    const float* b1 = (const float*)d_in[4];
    const float* W2 = (const float*)d_in[5];
    const float* b2 = (const float*)d_in[6];
    float* out = (float*)d_out;

    cudaFuncSetAttribute(mlp_hybrid_kernel,
                         cudaFuncAttributeMaxDynamicSharedMemorySize, SMEM_BYTES);

    dim3 gP(F_ / 32, B_ / 32);
    prep_kernel<<<gP, 256>>>(X);
    dim3 gA(B_ / ROWS, NEG);
    mlp_hybrid_kernel<<<gA, 256, SMEM_BYTES>>>(X, bw, W1, b1, W2, b2);
    mix_softmax_kernel<<<B_ / 4, 128>>>(D, out);
}